// round 13
// baseline (speedup 1.0000x reference)
#include <cuda_runtime.h>

#define DD 128
#define E_MAX 800000
#define R_MAX 512
#define SPLIT 8
#define SCHUNK 4096

// ---- scratch (device globals; no allocation allowed) ----
__device__ int   g_off[R_MAX + 1];
__device__ int   g_cursor[R_MAX];
__device__ int4  g_edges[E_MAX];           // sorted {src, dst, scale_bits, pad}
__device__ float g_Whi[2 * 256 * 128];     // stacked [loop_w; time_w], tf32 hi
__device__ float g_Wlo[2 * 256 * 128];     // tf32 lo

#define REDV4(ptr, v)                                                   \
    asm volatile("red.global.add.v4.f32 [%0], {%1,%2,%3,%4};"           \
                 :: "l"(ptr), "f"((v).x), "f"((v).y), "f"((v).z), "f"((v).w) \
                 : "memory")

#define MMA_TF32(c, a, b)                                               \
    asm volatile("mma.sync.aligned.m16n8k8.row.col.f32.tf32.tf32.f32 "  \
                 "{%0,%1,%2,%3}, {%4,%5,%6,%7}, {%8,%9}, {%0,%1,%2,%3};" \
                 : "+f"((c)[0]), "+f"((c)[1]), "+f"((c)[2]), "+f"((c)[3]) \
                 : "r"((a)[0]), "r"((a)[1]), "r"((a)[2]), "r"((a)[3]),  \
                   "r"((b)[0]), "r"((b)[1]))

__device__ __forceinline__ unsigned f2tf32(float v)
{
    unsigned r;
    asm("cvt.rna.tf32.f32 %0, %1;" : "=r"(r) : "f"(v));
    return r;
}

// ---------------------------------------------------------------------------
// Weight split: W' = [loop_w; time_w] (256x128) -> tf32 hi/lo, both layers.
// ---------------------------------------------------------------------------
__global__ void split_w_kernel(const float* __restrict__ lw1,
                               const float* __restrict__ tw1,
                               const float* __restrict__ lw2,
                               const float* __restrict__ tw2)
{
    int idx = blockIdx.x * blockDim.x + threadIdx.x;
    if (idx >= 2 * 256 * 128) return;
    int layer = idx >> 15;
    int k = (idx >> 7) & 255;
    int n = idx & 127;
    const float* lw = layer ? lw2 : lw1;
    const float* tw = layer ? tw2 : tw1;
    float v = (k < 128) ? lw[k * 128 + n] : tw[(k - 128) * 128 + n];
    unsigned hb = f2tf32(v);
    float lo = v - __uint_as_float(hb);
    g_Whi[idx] = __uint_as_float(hb);
    g_Wlo[idx] = __uint_as_float(f2tf32(lo));
}

// ---------------------------------------------------------------------------
// Tensor-core dense kernel (3xTF32), generalized k-range:
//   out[n,:] (+)= sum over kc in [kcBegin,kcEnd) of A-chunk @ W'-chunk
// where A-chunk = h rows for kc<4, dec(n)*prev rows for kc>=4.
// kcBegin=0,kcEnd=8,addOut=0 reproduces the R12 layer kernel exactly.
// ---------------------------------------------------------------------------
#define AS_STRIDE 36
#define WS_STRIDE 132
#define OFF_ASHI 0
#define OFF_ASLO (128 * AS_STRIDE)
#define OFF_WSHI (2 * 128 * AS_STRIDE)
#define OFF_WSLO (2 * 128 * AS_STRIDE + 32 * WS_STRIDE)
#define DENSE_SMEM_FLOATS (2 * 128 * AS_STRIDE + 2 * 32 * WS_STRIDE)

__global__ __launch_bounds__(256, 1)
void dense_tc_kernel(const float* __restrict__ h,
                     const float* __restrict__ prev,
                     const float* __restrict__ time_diff,
                     float* __restrict__ out, int N, int layer,
                     int kcBegin, int kcEnd, int addOut)
{
    extern __shared__ float sm[];
    float* AsHi = sm + OFF_ASHI;
    float* AsLo = sm + OFF_ASLO;
    float* WsHi = sm + OFF_WSHI;
    float* WsLo = sm + OFF_WSLO;

    const float* whi = g_Whi + layer * 32768;
    const float* wlo = g_Wlo + layer * 32768;

    const int tid  = threadIdx.x;
    const int wid  = tid >> 5;
    const int lane = tid & 31;
    const int g = lane >> 2;
    const int t = lane & 3;
    const int mbase = (wid & 3) * 32;
    const int nbase = (wid >> 2) * 64;
    const int tileBase = blockIdx.x * 128;

    const int sr  = tid >> 1;
    const int sc0 = (tid & 1) * 16;
    const int snode = tileBase + sr;
    const bool sok = (snode < N);
    const float dec = sok ? __expf(-__ldg(time_diff + snode) * 0.1f) : 0.f;

    const int skk  = tid >> 3;
    const int swc0 = (tid & 7) * 16;

    float acc[2][8][4];
#pragma unroll
    for (int mi = 0; mi < 2; mi++)
#pragma unroll
        for (int nt = 0; nt < 8; nt++)
#pragma unroll
            for (int c = 0; c < 4; c++) acc[mi][nt][c] = 0.f;

#pragma unroll 1
    for (int kc = kcBegin; kc < kcEnd; kc++) {
        __syncthreads();
        {
            float vals[16];
            if (sok) {
                const float* src = (kc < 4)
                    ? (h    + (size_t)snode * DD + kc * 32 + sc0)
                    : (prev + (size_t)snode * DD + (kc - 4) * 32 + sc0);
#pragma unroll
                for (int j = 0; j < 4; j++) {
                    float4 v = __ldg((const float4*)src + j);
                    vals[j * 4 + 0] = v.x; vals[j * 4 + 1] = v.y;
                    vals[j * 4 + 2] = v.z; vals[j * 4 + 3] = v.w;
                }
                if (kc >= 4) {
#pragma unroll
                    for (int j = 0; j < 16; j++) vals[j] *= dec;
                }
            } else {
#pragma unroll
                for (int j = 0; j < 16; j++) vals[j] = 0.f;
            }
            float his[16], los[16];
#pragma unroll
            for (int j = 0; j < 16; j++) {
                unsigned hb = f2tf32(vals[j]);
                his[j] = __uint_as_float(hb);
                los[j] = __uint_as_float(f2tf32(vals[j] - his[j]));
            }
            float* dhi = AsHi + sr * AS_STRIDE + sc0;
            float* dlo = AsLo + sr * AS_STRIDE + sc0;
#pragma unroll
            for (int j = 0; j < 4; j++) {
                ((float4*)dhi)[j] = make_float4(his[j*4], his[j*4+1], his[j*4+2], his[j*4+3]);
                ((float4*)dlo)[j] = make_float4(los[j*4], los[j*4+1], los[j*4+2], los[j*4+3]);
            }
        }
        {
            const float* shi = whi + (kc * 32 + skk) * 128 + swc0;
            const float* slo = wlo + (kc * 32 + skk) * 128 + swc0;
            float* dhi = WsHi + skk * WS_STRIDE + swc0;
            float* dlo = WsLo + skk * WS_STRIDE + swc0;
#pragma unroll
            for (int j = 0; j < 4; j++) {
                ((float4*)dhi)[j] = __ldg((const float4*)shi + j);
                ((float4*)dlo)[j] = __ldg((const float4*)slo + j);
            }
        }
        __syncthreads();

#pragma unroll
        for (int ks = 0; ks < 4; ks++) {
            const int k0 = ks * 8;
            unsigned ahi[2][4], alo[2][4];
#pragma unroll
            for (int mi = 0; mi < 2; mi++) {
                int r0 = (mbase + mi * 16 + g) * AS_STRIDE + k0 + t;
                int r1 = r0 + 8 * AS_STRIDE;
                ahi[mi][0] = __float_as_uint(AsHi[r0]);
                ahi[mi][1] = __float_as_uint(AsHi[r1]);
                ahi[mi][2] = __float_as_uint(AsHi[r0 + 4]);
                ahi[mi][3] = __float_as_uint(AsHi[r1 + 4]);
                alo[mi][0] = __float_as_uint(AsLo[r0]);
                alo[mi][1] = __float_as_uint(AsLo[r1]);
                alo[mi][2] = __float_as_uint(AsLo[r0 + 4]);
                alo[mi][3] = __float_as_uint(AsLo[r1 + 4]);
            }
            unsigned bhi[8][2], blo[8][2];
#pragma unroll
            for (int nt = 0; nt < 8; nt++) {
                int col = nbase + nt * 8 + g;
                int i0 = (k0 + t) * WS_STRIDE + col;
                int i1 = i0 + 4 * WS_STRIDE;
                bhi[nt][0] = __float_as_uint(WsHi[i0]);
                bhi[nt][1] = __float_as_uint(WsHi[i1]);
                blo[nt][0] = __float_as_uint(WsLo[i0]);
                blo[nt][1] = __float_as_uint(WsLo[i1]);
            }
#pragma unroll
            for (int mi = 0; mi < 2; mi++)
#pragma unroll
                for (int nt = 0; nt < 8; nt++) {
                    MMA_TF32(acc[mi][nt], ahi[mi], bhi[nt]);
                    MMA_TF32(acc[mi][nt], ahi[mi], blo[nt]);
                    MMA_TF32(acc[mi][nt], alo[mi], bhi[nt]);
                }
        }
    }

#pragma unroll
    for (int mi = 0; mi < 2; mi++) {
        int row0 = tileBase + mbase + mi * 16 + g;
        int row1 = row0 + 8;
#pragma unroll
        for (int nt = 0; nt < 8; nt++) {
            int col = nbase + nt * 8 + 2 * t;
            if (row0 < N) {
                float2* p = (float2*)(out + (size_t)row0 * DD + col);
                float2 v = make_float2(acc[mi][nt][0], acc[mi][nt][1]);
                if (addOut) { float2 o = *p; v.x += o.x; v.y += o.y; }
                *p = v;
            }
            if (row1 < N) {
                float2* p = (float2*)(out + (size_t)row1 * DD + col);
                float2 v = make_float2(acc[mi][nt][2], acc[mi][nt][3]);
                if (addOut) { float2 o = *p; v.x += o.x; v.y += o.y; }
                *p = v;
            }
        }
    }
}

// ---------------------------------------------------------------------------
// Sort pipeline: counting sort of edges by relation type (R12 exact).
// ---------------------------------------------------------------------------
__global__ void zero_kernel(int R)
{
    int i = blockIdx.x * blockDim.x + threadIdx.x;
    if (i <= R) g_off[i] = 0;
    if (i < R)  g_cursor[i] = 0;
}

__global__ __launch_bounds__(256)
void hist_kernel(const int* __restrict__ etyp, int E, int R)
{
    __shared__ int lh[R_MAX];
    for (int i = threadIdx.x; i < R; i += blockDim.x) lh[i] = 0;
    __syncthreads();

    const int E4 = E >> 2;
    for (int q = blockIdx.x * blockDim.x + threadIdx.x; q < E4;
         q += gridDim.x * blockDim.x) {
        int4 tv = __ldg((const int4*)etyp + q);
        atomicAdd(&lh[tv.x], 1);
        atomicAdd(&lh[tv.y], 1);
        atomicAdd(&lh[tv.z], 1);
        atomicAdd(&lh[tv.w], 1);
    }
    int rem0 = E4 << 2;
    for (int e = rem0 + blockIdx.x * blockDim.x + threadIdx.x; e < E;
         e += gridDim.x * blockDim.x)
        atomicAdd(&lh[__ldg(etyp + e)], 1);
    __syncthreads();

    for (int i = threadIdx.x; i < R; i += blockDim.x) {
        int v = lh[i];
        if (v) atomicAdd(&g_off[i + 1], v);
    }
}

__global__ __launch_bounds__(512)
void scan_kernel(int R)
{
    __shared__ int buf[512];
    const int tid = threadIdx.x;
    buf[tid] = (tid <= R) ? g_off[tid] : 0;
    __syncthreads();
#pragma unroll
    for (int d = 1; d < 512; d <<= 1) {
        int v = (tid >= d) ? buf[tid - d] : 0;
        __syncthreads();
        buf[tid] += v;
        __syncthreads();
    }
    if (tid <= R) g_off[tid] = buf[tid];
}

__global__ __launch_bounds__(256)
void scatter_kernel(const int* __restrict__ esrc,
                    const int* __restrict__ edst,
                    const int* __restrict__ etyp,
                    const float* __restrict__ enorm,
                    const float* __restrict__ nnorm,
                    int E, int R)
{
    __shared__ int lbase[R_MAX];
    __shared__ int lcur[R_MAX];

    const int e0 = blockIdx.x * SCHUNK;
    const int e1 = min(e0 + SCHUNK, E);

    for (int i = threadIdx.x; i < R; i += blockDim.x) {
        lbase[i] = 0;
        lcur[i]  = 0;
    }
    __syncthreads();

    for (int e = e0 + threadIdx.x; e < e1; e += blockDim.x)
        atomicAdd(&lbase[__ldg(etyp + e)], 1);
    __syncthreads();

    for (int i = threadIdx.x; i < R; i += blockDim.x) {
        int cnt = lbase[i];
        lbase[i] = cnt ? (g_off[i] + atomicAdd(&g_cursor[i], cnt)) : 0;
    }
    __syncthreads();

    for (int e = e0 + threadIdx.x; e < e1; e += blockDim.x) {
        int t = __ldg(etyp + e);
        int d = __ldg(edst + e);
        int pos = lbase[t] + atomicAdd(&lcur[t], 1);
        float sc = __ldg(enorm + e) * __ldg(nnorm + d);
        g_edges[pos] = make_int4(__ldg(esrc + e), d, __float_as_int(sc), 0);
    }
}

// ---------------------------------------------------------------------------
// Sorted edge kernel, 2-wide (R12 exact).
// ---------------------------------------------------------------------------
__global__ __launch_bounds__(256)
void edge_sorted_kernel(const float* __restrict__ h,
                        const float* __restrict__ W,
                        float* __restrict__ out)
{
    const int t    = blockIdx.x;
    const int lane = threadIdx.x & 31;
    const int warp = threadIdx.x >> 5;

    const int start = g_off[t];
    const int end   = g_off[t + 1];
    if (start >= end) return;

    const float4* wp = (const float4*)(W + (size_t)t * 512) + lane * 4;
    const float4 w0 = __ldg(wp + 0);
    const float4 w1 = __ldg(wp + 1);
    const float4 w2 = __ldg(wp + 2);
    const float4 w3 = __ldg(wp + 3);

    const int stride = 8 * SPLIT;
    int e = start + blockIdx.y * 8 + warp;

    for (; e + stride < end; e += 2 * stride) {
        const int4 mdA = __ldg(g_edges + e);
        const int4 mdB = __ldg(g_edges + e + stride);

        float4 hA = __ldg((const float4*)(h + (size_t)mdA.x * DD) + lane);
        float4 hB = __ldg((const float4*)(h + (size_t)mdB.x * DD) + lane);

        const float scA = __int_as_float(mdA.z);
        const float scB = __int_as_float(mdB.z);

        float4 mA, mB;
        mA.x = hA.x * w0.x + hA.y * w1.x + hA.z * w2.x + hA.w * w3.x;
        mA.y = hA.x * w0.y + hA.y * w1.y + hA.z * w2.y + hA.w * w3.y;
        mA.z = hA.x * w0.z + hA.y * w1.z + hA.z * w2.z + hA.w * w3.z;
        mA.w = hA.x * w0.w + hA.y * w1.w + hA.z * w2.w + hA.w * w3.w;
        mB.x = hB.x * w0.x + hB.y * w1.x + hB.z * w2.x + hB.w * w3.x;
        mB.y = hB.x * w0.y + hB.y * w1.y + hB.z * w2.y + hB.w * w3.y;
        mB.z = hB.x * w0.z + hB.y * w1.z + hB.z * w2.z + hB.w * w3.z;
        mB.w = hB.x * w0.w + hB.y * w1.w + hB.z * w2.w + hB.w * w3.w;
        mA.x *= scA; mA.y *= scA; mA.z *= scA; mA.w *= scA;
        mB.x *= scB; mB.y *= scB; mB.z *= scB; mB.w *= scB;

        REDV4(out + (size_t)mdA.y * DD + lane * 4, mA);
        REDV4(out + (size_t)mdB.y * DD + lane * 4, mB);
    }

    if (e < end) {
        const int4 md = __ldg(g_edges + e);
        float4 hv = __ldg((const float4*)(h + (size_t)md.x * DD) + lane);
        const float sc = __int_as_float(md.z);

        float4 m;
        m.x = hv.x * w0.x + hv.y * w1.x + hv.z * w2.x + hv.w * w3.x;
        m.y = hv.x * w0.y + hv.y * w1.y + hv.z * w2.y + hv.w * w3.y;
        m.z = hv.x * w0.z + hv.y * w1.z + hv.z * w2.z + hv.w * w3.z;
        m.w = hv.x * w0.w + hv.y * w1.w + hv.z * w2.w + hv.w * w3.w;
        m.x *= sc; m.y *= sc; m.z *= sc; m.w *= sc;

        REDV4(out + (size_t)md.y * DD + lane * 4, m);
    }
}

__global__ void relu_kernel(float4* __restrict__ x, int n4)
{
    int i = blockIdx.x * blockDim.x + threadIdx.x;
    if (i < n4) {
        float4 v = x[i];
        v.x = fmaxf(v.x, 0.f);
        v.y = fmaxf(v.y, 0.f);
        v.z = fmaxf(v.z, 0.f);
        v.w = fmaxf(v.w, 0.f);
        x[i] = v;
    }
}

extern "C" void kernel_launch(void* const* d_in, const int* in_sizes, int n_in,
                              void* d_out, int out_size)
{
    const float* h   = (const float*)d_in[0];
    const float* fp  = (const float*)d_in[1];
    const float* sp  = (const float*)d_in[2];
    const float* td  = (const float*)d_in[3];
    const int*   es  = (const int*)  d_in[4];
    const int*   ed  = (const int*)  d_in[5];
    const int*   et  = (const int*)  d_in[6];
    const float* en  = (const float*)d_in[7];
    const float* nn  = (const float*)d_in[8];
    const float* W1  = (const float*)d_in[9];
    const float* W2  = (const float*)d_in[10];
    const float* lw1 = (const float*)d_in[11];
    const float* lw2 = (const float*)d_in[12];
    const float* tw1 = (const float*)d_in[13];
    const float* tw2 = (const float*)d_in[14];

    const int N = in_sizes[3];            // time_diff is (N,1)
    const int E = in_sizes[4];            // edge_src is (E,)
    const int R = in_sizes[9] / 512;      // W1 is (R, 512)

    float* h1 = (float*)d_out;
    float* h2 = h1 + (size_t)N * DD;

    const int denseBlocks   = (N + 127) / 128;
    const int scatterBlocks = (E + SCHUNK - 1) / SCHUNK;
    const int denseSmem     = DENSE_SMEM_FLOATS * sizeof(float);
    const int n4 = N * DD / 4;
    dim3 edgeGrid(R, SPLIT);

    cudaFuncSetAttribute(dense_tc_kernel,
                         cudaFuncAttributeMaxDynamicSharedMemorySize,
                         denseSmem);

    static cudaStream_t s2 = nullptr;
    static cudaEvent_t evFork = nullptr, evJoin = nullptr, evT2 = nullptr;
    if (s2 == nullptr) {
        cudaStreamCreateWithFlags(&s2, cudaStreamNonBlocking);
        cudaEventCreateWithFlags(&evFork, cudaEventDisableTiming);
        cudaEventCreateWithFlags(&evJoin, cudaEventDisableTiming);
        cudaEventCreateWithFlags(&evT2, cudaEventDisableTiming);
    }

    // ---- fork: sort pipeline + layer2 time-GEMM on s2;
    //      weight split + layer1 dense on main stream ----
    cudaEventRecord(evFork, 0);
    cudaStreamWaitEvent(s2, evFork, 0);

    zero_kernel   <<<(R + 256) / 256, 256, 0, s2>>>(R);
    hist_kernel   <<<256, 256, 0, s2>>>(et, E, R);
    scan_kernel   <<<1, 512, 0, s2>>>(R);
    scatter_kernel<<<scatterBlocks, 256, 0, s2>>>(es, ed, et, en, nn, E, R);
    cudaEventRecord(evJoin, s2);

    split_w_kernel<<<(2 * 256 * 128 + 255) / 256, 256>>>(lw1, tw1, lw2, tw2);
    dense_tc_kernel<<<denseBlocks, 256, denseSmem>>>(h, fp, td, h1, N, 0,
                                                     0, 8, 0);

    // T2 = dec * (second_prev @ time_w2) -> h2, on s2 (needs split_w done —
    // s2 waits on main via evFork? No: fork was before split. Wait explicitly.)
    // Record a second fork point after split_w on main:
    // (evJoin already recorded; reuse evT2 as the split-done marker is not
    // possible — instead chain T2 after scatter AND after a wait on a
    // split-done event.)
    static cudaEvent_t evSplit = nullptr;
    if (evSplit == nullptr)
        cudaEventCreateWithFlags(&evSplit, cudaEventDisableTiming);
    // NOTE: record split-done event right after split_w launch order matters;
    // we record it here (after dense1 launch) — split_w completed before
    // dense1 finishes, and T2 only starts after scatter (~same time), so
    // recording after dense1 launch is still correct ordering-wise because
    // events capture stream position, and split_w precedes this point.
    cudaEventRecord(evSplit, 0);
    cudaStreamWaitEvent(s2, evSplit, 0);
    dense_tc_kernel<<<denseBlocks, 256, denseSmem, s2>>>(nullptr, sp, td, h2,
                                                         N, 1, 4, 8, 0);
    cudaEventRecord(evT2, s2);

    // ---- join: edge1 needs sorted edges + dense1 fill ----
    cudaStreamWaitEvent(0, evJoin, 0);
    edge_sorted_kernel<<<edgeGrid, 256>>>(h, W1, h1);

    // ---- layer 2: loop-half GEMM (h1 @ loop_w2) added onto T2 ----
    cudaStreamWaitEvent(0, evT2, 0);
    dense_tc_kernel<<<denseBlocks, 256, denseSmem>>>(h1, nullptr, td, h2, N, 1,
                                                     0, 4, 1);
    edge_sorted_kernel<<<edgeGrid, 256>>>(h1, W2, h2);
    relu_kernel<<<(n4 + 255) / 256, 256>>>((float4*)h2, n4);
}

// round 14
// speedup vs baseline: 1.0357x; 1.0357x over previous
#include <cuda_runtime.h>

#define DD 128
#define E_MAX 800000
#define R_MAX 512
#define SPLIT 8
#define SCHUNK 4096

// ---- scratch (device globals; no allocation allowed) ----
__device__ int   g_off[R_MAX + 1];
__device__ int   g_cursor[R_MAX];
__device__ int4  g_edges[E_MAX];           // sorted {src, dst, scale_bits, pad}
__device__ float g_Whi[2 * 256 * 128];     // stacked [loop_w; time_w], tf32 hi
__device__ float g_Wlo[2 * 256 * 128];     // tf32 lo

#define REDV4(ptr, v)                                                   \
    asm volatile("red.global.add.v4.f32 [%0], {%1,%2,%3,%4};"           \
                 :: "l"(ptr), "f"((v).x), "f"((v).y), "f"((v).z), "f"((v).w) \
                 : "memory")

#define MMA_TF32(c, a, b)                                               \
    asm volatile("mma.sync.aligned.m16n8k8.row.col.f32.tf32.tf32.f32 "  \
                 "{%0,%1,%2,%3}, {%4,%5,%6,%7}, {%8,%9}, {%0,%1,%2,%3};" \
                 : "+f"((c)[0]), "+f"((c)[1]), "+f"((c)[2]), "+f"((c)[3]) \
                 : "r"((a)[0]), "r"((a)[1]), "r"((a)[2]), "r"((a)[3]),  \
                   "r"((b)[0]), "r"((b)[1]))

__device__ __forceinline__ unsigned f2tf32(float v)
{
    unsigned r;
    asm("cvt.rna.tf32.f32 %0, %1;" : "=r"(r) : "f"(v));
    return r;
}

// ---------------------------------------------------------------------------
// Weight split: W' = [loop_w; time_w] (256x128) -> tf32 hi/lo, both layers.
// ---------------------------------------------------------------------------
__global__ void split_w_kernel(const float* __restrict__ lw1,
                               const float* __restrict__ tw1,
                               const float* __restrict__ lw2,
                               const float* __restrict__ tw2)
{
    int idx = blockIdx.x * blockDim.x + threadIdx.x;
    if (idx >= 2 * 256 * 128) return;
    int layer = idx >> 15;
    int k = (idx >> 7) & 255;
    int n = idx & 127;
    const float* lw = layer ? lw2 : lw1;
    const float* tw = layer ? tw2 : tw1;
    float v = (k < 128) ? lw[k * 128 + n] : tw[(k - 128) * 128 + n];
    unsigned hb = f2tf32(v);
    float lo = v - __uint_as_float(hb);
    g_Whi[idx] = __uint_as_float(hb);
    g_Wlo[idx] = __uint_as_float(f2tf32(lo));
}

// ---------------------------------------------------------------------------
// Tensor-core dense kernel (3xTF32), DOUBLE-BUFFERED staging:
//   out[n,:] = [h[n,:], dec(n)*prev[n,:]] @ W'  (K=256)
// Stage kc+1 (LDG+cvt+STS) while MMAs consume kc; one sync per iteration.
// ---------------------------------------------------------------------------
#define AS_STRIDE 36
#define WS_STRIDE 132
#define A_BUF (128 * AS_STRIDE)     // 4608 floats per A half-buffer
#define W_BUF (32 * WS_STRIDE)      // 4224 floats per W half-buffer
#define OFF_ASHI(b) ((b) * A_BUF)
#define OFF_ASLO(b) (2 * A_BUF + (b) * A_BUF)
#define OFF_WSHI(b) (4 * A_BUF + (b) * W_BUF)
#define OFF_WSLO(b) (4 * A_BUF + 2 * W_BUF + (b) * W_BUF)
#define DENSE_SMEM_FLOATS (4 * A_BUF + 4 * W_BUF)   // 35328 floats = 141312 B

__device__ __forceinline__ void stage_A(const float* __restrict__ h,
                                        const float* __restrict__ prev,
                                        int kc, int snode, bool sok, float dec,
                                        int sr, int sc0,
                                        float* __restrict__ AsHi,
                                        float* __restrict__ AsLo)
{
    const float* src = (kc < 4)
        ? (h    + (size_t)snode * DD + kc * 32 + sc0)
        : (prev + (size_t)snode * DD + (kc - 4) * 32 + sc0);
    float* dhi = AsHi + sr * AS_STRIDE + sc0;
    float* dlo = AsLo + sr * AS_STRIDE + sc0;
#pragma unroll
    for (int j = 0; j < 4; j++) {
        float4 v = sok ? __ldg((const float4*)src + j)
                       : make_float4(0.f, 0.f, 0.f, 0.f);
        if (kc >= 4) { v.x *= dec; v.y *= dec; v.z *= dec; v.w *= dec; }
        float4 hi, lo;
        hi.x = __uint_as_float(f2tf32(v.x));
        hi.y = __uint_as_float(f2tf32(v.y));
        hi.z = __uint_as_float(f2tf32(v.z));
        hi.w = __uint_as_float(f2tf32(v.w));
        lo.x = __uint_as_float(f2tf32(v.x - hi.x));
        lo.y = __uint_as_float(f2tf32(v.y - hi.y));
        lo.z = __uint_as_float(f2tf32(v.z - hi.z));
        lo.w = __uint_as_float(f2tf32(v.w - hi.w));
        ((float4*)dhi)[j] = hi;
        ((float4*)dlo)[j] = lo;
    }
}

__device__ __forceinline__ void stage_W(const float* __restrict__ whi,
                                        const float* __restrict__ wlo,
                                        int kc, int skk, int swc0,
                                        float* __restrict__ WsHi,
                                        float* __restrict__ WsLo)
{
    const float* shi = whi + (kc * 32 + skk) * 128 + swc0;
    const float* slo = wlo + (kc * 32 + skk) * 128 + swc0;
    float* dhi = WsHi + skk * WS_STRIDE + swc0;
    float* dlo = WsLo + skk * WS_STRIDE + swc0;
#pragma unroll
    for (int j = 0; j < 4; j++) {
        ((float4*)dhi)[j] = __ldg((const float4*)shi + j);
        ((float4*)dlo)[j] = __ldg((const float4*)slo + j);
    }
}

__global__ __launch_bounds__(256, 1)
void dense_tc_kernel(const float* __restrict__ h,
                     const float* __restrict__ prev,
                     const float* __restrict__ time_diff,
                     float* __restrict__ out, int N, int layer)
{
    extern __shared__ float sm[];

    const float* whi = g_Whi + layer * 32768;
    const float* wlo = g_Wlo + layer * 32768;

    const int tid  = threadIdx.x;
    const int wid  = tid >> 5;
    const int lane = tid & 31;
    const int g = lane >> 2;
    const int t = lane & 3;
    const int mbase = (wid & 3) * 32;
    const int nbase = (wid >> 2) * 64;
    const int tileBase = blockIdx.x * 128;

    const int sr  = tid >> 1;
    const int sc0 = (tid & 1) * 16;
    const int snode = tileBase + sr;
    const bool sok = (snode < N);
    const float dec = sok ? __expf(-__ldg(time_diff + snode) * 0.1f) : 0.f;

    const int skk  = tid >> 3;
    const int swc0 = (tid & 7) * 16;

    float acc[2][8][4];
#pragma unroll
    for (int mi = 0; mi < 2; mi++)
#pragma unroll
        for (int nt = 0; nt < 8; nt++)
#pragma unroll
            for (int c = 0; c < 4; c++) acc[mi][nt][c] = 0.f;

    // prologue: stage kc=0 into buffer 0
    stage_A(h, prev, 0, snode, sok, dec, sr, sc0,
            sm + OFF_ASHI(0), sm + OFF_ASLO(0));
    stage_W(whi, wlo, 0, skk, swc0, sm + OFF_WSHI(0), sm + OFF_WSLO(0));
    __syncthreads();

#pragma unroll 1
    for (int kc = 0; kc < 8; kc++) {
        const int cur = kc & 1;
        // stage next chunk into the other buffer (overlaps with MMAs below)
        if (kc < 7) {
            const int nb = (kc + 1) & 1;
            stage_A(h, prev, kc + 1, snode, sok, dec, sr, sc0,
                    sm + OFF_ASHI(nb), sm + OFF_ASLO(nb));
            stage_W(whi, wlo, kc + 1, skk, swc0,
                    sm + OFF_WSHI(nb), sm + OFF_WSLO(nb));
        }

        const float* AsHi = sm + OFF_ASHI(cur);
        const float* AsLo = sm + OFF_ASLO(cur);
        const float* WsHi = sm + OFF_WSHI(cur);
        const float* WsLo = sm + OFF_WSLO(cur);

#pragma unroll
        for (int ks = 0; ks < 4; ks++) {
            const int k0 = ks * 8;
            unsigned ahi[2][4], alo[2][4];
#pragma unroll
            for (int mi = 0; mi < 2; mi++) {
                int r0 = (mbase + mi * 16 + g) * AS_STRIDE + k0 + t;
                int r1 = r0 + 8 * AS_STRIDE;
                ahi[mi][0] = __float_as_uint(AsHi[r0]);
                ahi[mi][1] = __float_as_uint(AsHi[r1]);
                ahi[mi][2] = __float_as_uint(AsHi[r0 + 4]);
                ahi[mi][3] = __float_as_uint(AsHi[r1 + 4]);
                alo[mi][0] = __float_as_uint(AsLo[r0]);
                alo[mi][1] = __float_as_uint(AsLo[r1]);
                alo[mi][2] = __float_as_uint(AsLo[r0 + 4]);
                alo[mi][3] = __float_as_uint(AsLo[r1 + 4]);
            }
            unsigned bhi[8][2], blo[8][2];
#pragma unroll
            for (int nt = 0; nt < 8; nt++) {
                int col = nbase + nt * 8 + g;
                int i0 = (k0 + t) * WS_STRIDE + col;
                int i1 = i0 + 4 * WS_STRIDE;
                bhi[nt][0] = __float_as_uint(WsHi[i0]);
                bhi[nt][1] = __float_as_uint(WsHi[i1]);
                blo[nt][0] = __float_as_uint(WsLo[i0]);
                blo[nt][1] = __float_as_uint(WsLo[i1]);
            }
#pragma unroll
            for (int mi = 0; mi < 2; mi++)
#pragma unroll
                for (int nt = 0; nt < 8; nt++) {
                    MMA_TF32(acc[mi][nt], ahi[mi], bhi[nt]);
                    MMA_TF32(acc[mi][nt], ahi[mi], blo[nt]);
                    MMA_TF32(acc[mi][nt], alo[mi], bhi[nt]);
                }
        }
        __syncthreads();
    }

#pragma unroll
    for (int mi = 0; mi < 2; mi++) {
        int row0 = tileBase + mbase + mi * 16 + g;
        int row1 = row0 + 8;
#pragma unroll
        for (int nt = 0; nt < 8; nt++) {
            int col = nbase + nt * 8 + 2 * t;
            if (row0 < N)
                *(float2*)(out + (size_t)row0 * DD + col) =
                    make_float2(acc[mi][nt][0], acc[mi][nt][1]);
            if (row1 < N)
                *(float2*)(out + (size_t)row1 * DD + col) =
                    make_float2(acc[mi][nt][2], acc[mi][nt][3]);
        }
    }
}

// ---------------------------------------------------------------------------
// Sort pipeline: counting sort of edges by relation type (R12 exact).
// ---------------------------------------------------------------------------
__global__ void zero_kernel(int R)
{
    int i = blockIdx.x * blockDim.x + threadIdx.x;
    if (i <= R) g_off[i] = 0;
    if (i < R)  g_cursor[i] = 0;
}

__global__ __launch_bounds__(256)
void hist_kernel(const int* __restrict__ etyp, int E, int R)
{
    __shared__ int lh[R_MAX];
    for (int i = threadIdx.x; i < R; i += blockDim.x) lh[i] = 0;
    __syncthreads();

    const int E4 = E >> 2;
    for (int q = blockIdx.x * blockDim.x + threadIdx.x; q < E4;
         q += gridDim.x * blockDim.x) {
        int4 tv = __ldg((const int4*)etyp + q);
        atomicAdd(&lh[tv.x], 1);
        atomicAdd(&lh[tv.y], 1);
        atomicAdd(&lh[tv.z], 1);
        atomicAdd(&lh[tv.w], 1);
    }
    int rem0 = E4 << 2;
    for (int e = rem0 + blockIdx.x * blockDim.x + threadIdx.x; e < E;
         e += gridDim.x * blockDim.x)
        atomicAdd(&lh[__ldg(etyp + e)], 1);
    __syncthreads();

    for (int i = threadIdx.x; i < R; i += blockDim.x) {
        int v = lh[i];
        if (v) atomicAdd(&g_off[i + 1], v);
    }
}

__global__ __launch_bounds__(512)
void scan_kernel(int R)
{
    __shared__ int buf[512];
    const int tid = threadIdx.x;
    buf[tid] = (tid <= R) ? g_off[tid] : 0;
    __syncthreads();
#pragma unroll
    for (int d = 1; d < 512; d <<= 1) {
        int v = (tid >= d) ? buf[tid - d] : 0;
        __syncthreads();
        buf[tid] += v;
        __syncthreads();
    }
    if (tid <= R) g_off[tid] = buf[tid];
}

__global__ __launch_bounds__(256)
void scatter_kernel(const int* __restrict__ esrc,
                    const int* __restrict__ edst,
                    const int* __restrict__ etyp,
                    const float* __restrict__ enorm,
                    const float* __restrict__ nnorm,
                    int E, int R)
{
    __shared__ int lbase[R_MAX];
    __shared__ int lcur[R_MAX];

    const int e0 = blockIdx.x * SCHUNK;
    const int e1 = min(e0 + SCHUNK, E);

    for (int i = threadIdx.x; i < R; i += blockDim.x) {
        lbase[i] = 0;
        lcur[i]  = 0;
    }
    __syncthreads();

    for (int e = e0 + threadIdx.x; e < e1; e += blockDim.x)
        atomicAdd(&lbase[__ldg(etyp + e)], 1);
    __syncthreads();

    for (int i = threadIdx.x; i < R; i += blockDim.x) {
        int cnt = lbase[i];
        lbase[i] = cnt ? (g_off[i] + atomicAdd(&g_cursor[i], cnt)) : 0;
    }
    __syncthreads();

    for (int e = e0 + threadIdx.x; e < e1; e += blockDim.x) {
        int t = __ldg(etyp + e);
        int d = __ldg(edst + e);
        int pos = lbase[t] + atomicAdd(&lcur[t], 1);
        float sc = __ldg(enorm + e) * __ldg(nnorm + d);
        g_edges[pos] = make_int4(__ldg(esrc + e), d, __float_as_int(sc), 0);
    }
}

// ---------------------------------------------------------------------------
// Sorted edge kernel, 2-wide (R12 exact).
// ---------------------------------------------------------------------------
__global__ __launch_bounds__(256)
void edge_sorted_kernel(const float* __restrict__ h,
                        const float* __restrict__ W,
                        float* __restrict__ out)
{
    const int t    = blockIdx.x;
    const int lane = threadIdx.x & 31;
    const int warp = threadIdx.x >> 5;

    const int start = g_off[t];
    const int end   = g_off[t + 1];
    if (start >= end) return;

    const float4* wp = (const float4*)(W + (size_t)t * 512) + lane * 4;
    const float4 w0 = __ldg(wp + 0);
    const float4 w1 = __ldg(wp + 1);
    const float4 w2 = __ldg(wp + 2);
    const float4 w3 = __ldg(wp + 3);

    const int stride = 8 * SPLIT;
    int e = start + blockIdx.y * 8 + warp;

    for (; e + stride < end; e += 2 * stride) {
        const int4 mdA = __ldg(g_edges + e);
        const int4 mdB = __ldg(g_edges + e + stride);

        float4 hA = __ldg((const float4*)(h + (size_t)mdA.x * DD) + lane);
        float4 hB = __ldg((const float4*)(h + (size_t)mdB.x * DD) + lane);

        const float scA = __int_as_float(mdA.z);
        const float scB = __int_as_float(mdB.z);

        float4 mA, mB;
        mA.x = hA.x * w0.x + hA.y * w1.x + hA.z * w2.x + hA.w * w3.x;
        mA.y = hA.x * w0.y + hA.y * w1.y + hA.z * w2.y + hA.w * w3.y;
        mA.z = hA.x * w0.z + hA.y * w1.z + hA.z * w2.z + hA.w * w3.z;
        mA.w = hA.x * w0.w + hA.y * w1.w + hA.z * w2.w + hA.w * w3.w;
        mB.x = hB.x * w0.x + hB.y * w1.x + hB.z * w2.x + hB.w * w3.x;
        mB.y = hB.x * w0.y + hB.y * w1.y + hB.z * w2.y + hB.w * w3.y;
        mB.z = hB.x * w0.z + hB.y * w1.z + hB.z * w2.z + hB.w * w3.z;
        mB.w = hB.x * w0.w + hB.y * w1.w + hB.z * w2.w + hB.w * w3.w;
        mA.x *= scA; mA.y *= scA; mA.z *= scA; mA.w *= scA;
        mB.x *= scB; mB.y *= scB; mB.z *= scB; mB.w *= scB;

        REDV4(out + (size_t)mdA.y * DD + lane * 4, mA);
        REDV4(out + (size_t)mdB.y * DD + lane * 4, mB);
    }

    if (e < end) {
        const int4 md = __ldg(g_edges + e);
        float4 hv = __ldg((const float4*)(h + (size_t)md.x * DD) + lane);
        const float sc = __int_as_float(md.z);

        float4 m;
        m.x = hv.x * w0.x + hv.y * w1.x + hv.z * w2.x + hv.w * w3.x;
        m.y = hv.x * w0.y + hv.y * w1.y + hv.z * w2.y + hv.w * w3.y;
        m.z = hv.x * w0.z + hv.y * w1.z + hv.z * w2.z + hv.w * w3.z;
        m.w = hv.x * w0.w + hv.y * w1.w + hv.z * w2.w + hv.w * w3.w;
        m.x *= sc; m.y *= sc; m.z *= sc; m.w *= sc;

        REDV4(out + (size_t)md.y * DD + lane * 4, m);
    }
}

__global__ void relu_kernel(float4* __restrict__ x, int n4)
{
    int i = blockIdx.x * blockDim.x + threadIdx.x;
    if (i < n4) {
        float4 v = x[i];
        v.x = fmaxf(v.x, 0.f);
        v.y = fmaxf(v.y, 0.f);
        v.z = fmaxf(v.z, 0.f);
        v.w = fmaxf(v.w, 0.f);
        x[i] = v;
    }
}

extern "C" void kernel_launch(void* const* d_in, const int* in_sizes, int n_in,
                              void* d_out, int out_size)
{
    const float* h   = (const float*)d_in[0];
    const float* fp  = (const float*)d_in[1];
    const float* sp  = (const float*)d_in[2];
    const float* td  = (const float*)d_in[3];
    const int*   es  = (const int*)  d_in[4];
    const int*   ed  = (const int*)  d_in[5];
    const int*   et  = (const int*)  d_in[6];
    const float* en  = (const float*)d_in[7];
    const float* nn  = (const float*)d_in[8];
    const float* W1  = (const float*)d_in[9];
    const float* W2  = (const float*)d_in[10];
    const float* lw1 = (const float*)d_in[11];
    const float* lw2 = (const float*)d_in[12];
    const float* tw1 = (const float*)d_in[13];
    const float* tw2 = (const float*)d_in[14];

    const int N = in_sizes[3];            // time_diff is (N,1)
    const int E = in_sizes[4];            // edge_src is (E,)
    const int R = in_sizes[9] / 512;      // W1 is (R, 512)

    float* h1 = (float*)d_out;
    float* h2 = h1 + (size_t)N * DD;

    const int denseBlocks   = (N + 127) / 128;
    const int scatterBlocks = (E + SCHUNK - 1) / SCHUNK;
    const int denseSmem     = DENSE_SMEM_FLOATS * sizeof(float);
    const int n4 = N * DD / 4;
    dim3 edgeGrid(R, SPLIT);

    cudaFuncSetAttribute(dense_tc_kernel,
                         cudaFuncAttributeMaxDynamicSharedMemorySize,
                         denseSmem);

    static cudaStream_t s2 = nullptr;
    static cudaEvent_t evFork = nullptr, evJoin = nullptr;
    if (s2 == nullptr) {
        cudaStreamCreateWithFlags(&s2, cudaStreamNonBlocking);
        cudaEventCreateWithFlags(&evFork, cudaEventDisableTiming);
        cudaEventCreateWithFlags(&evJoin, cudaEventDisableTiming);
    }

    // ---- fork: sort pipeline on s2, weight split + dense1 on main stream ----
    cudaEventRecord(evFork, 0);
    cudaStreamWaitEvent(s2, evFork, 0);

    zero_kernel   <<<(R + 256) / 256, 256, 0, s2>>>(R);
    hist_kernel   <<<256, 256, 0, s2>>>(et, E, R);
    scan_kernel   <<<1, 512, 0, s2>>>(R);
    scatter_kernel<<<scatterBlocks, 256, 0, s2>>>(es, ed, et, en, nn, E, R);
    cudaEventRecord(evJoin, s2);

    split_w_kernel<<<(2 * 256 * 128 + 255) / 256, 256>>>(lw1, tw1, lw2, tw2);
    dense_tc_kernel<<<denseBlocks, 256, denseSmem>>>(h, fp, td, h1, N, 0);

    // ---- join: edge1 needs both the sorted edges and the dense fill ----
    cudaStreamWaitEvent(0, evJoin, 0);
    edge_sorted_kernel<<<edgeGrid, 256>>>(h, W1, h1);

    // ---- layer 2 ----
    dense_tc_kernel<<<denseBlocks, 256, denseSmem>>>(h1, sp, td, h2, N, 1);
    edge_sorted_kernel<<<edgeGrid, 256>>>(h1, W2, h2);
    relu_kernel<<<(n4 + 255) / 256, 256>>>((float4*)h2, n4);
}

// round 15
// speedup vs baseline: 1.0376x; 1.0019x over previous
#include <cuda_runtime.h>

#define DD 128
#define E_MAX 800000
#define R_MAX 512
#define SPLIT 8
#define SCHUNK 4096

// ---- scratch (device globals; no allocation allowed) ----
__device__ int   g_off[R_MAX + 1];
__device__ int   g_cursor[R_MAX];
__device__ int4  g_edges[E_MAX];           // sorted {src, dst, scale_bits, pad}
__device__ float g_Whi[2 * 256 * 128];     // stacked [loop_w; time_w], tf32 hi
__device__ float g_Wlo[2 * 256 * 128];     // tf32 lo

#define REDV4(ptr, v)                                                   \
    asm volatile("red.global.add.v4.f32 [%0], {%1,%2,%3,%4};"           \
                 :: "l"(ptr), "f"((v).x), "f"((v).y), "f"((v).z), "f"((v).w) \
                 : "memory")

#define MMA_TF32(c, a, b)                                               \
    asm volatile("mma.sync.aligned.m16n8k8.row.col.f32.tf32.tf32.f32 "  \
                 "{%0,%1,%2,%3}, {%4,%5,%6,%7}, {%8,%9}, {%0,%1,%2,%3};" \
                 : "+f"((c)[0]), "+f"((c)[1]), "+f"((c)[2]), "+f"((c)[3]) \
                 : "r"((a)[0]), "r"((a)[1]), "r"((a)[2]), "r"((a)[3]),  \
                   "r"((b)[0]), "r"((b)[1]))

#define CP_ASYNC16(smem_u32, gptr)                                      \
    asm volatile("cp.async.cg.shared.global [%0], [%1], 16;"            \
                 :: "r"(smem_u32), "l"(gptr) : "memory")

__device__ __forceinline__ unsigned f2tf32(float v)
{
    unsigned r;
    asm("cvt.rna.tf32.f32 %0, %1;" : "=r"(r) : "f"(v));
    return r;
}

// ---------------------------------------------------------------------------
// Weight split: W' = [loop_w; time_w] (256x128) -> tf32 hi/lo, both layers.
// ---------------------------------------------------------------------------
__global__ void split_w_kernel(const float* __restrict__ lw1,
                               const float* __restrict__ tw1,
                               const float* __restrict__ lw2,
                               const float* __restrict__ tw2)
{
    int idx = blockIdx.x * blockDim.x + threadIdx.x;
    if (idx >= 2 * 256 * 128) return;
    int layer = idx >> 15;
    int k = (idx >> 7) & 255;
    int n = idx & 127;
    const float* lw = layer ? lw2 : lw1;
    const float* tw = layer ? tw2 : tw1;
    float v = (k < 128) ? lw[k * 128 + n] : tw[(k - 128) * 128 + n];
    unsigned hb = f2tf32(v);
    float lo = v - __uint_as_float(hb);
    g_Whi[idx] = __uint_as_float(hb);
    g_Wlo[idx] = __uint_as_float(f2tf32(lo));
}

// ---------------------------------------------------------------------------
// Tensor-core dense kernel (3xTF32), R12 structure; W staged via cp.async
// (register-neutral, latency hidden behind the A-stage LDG+cvt work):
//   out[n,:] = [h[n,:], dec(n)*prev[n,:]] @ W'  (K=256)
// ---------------------------------------------------------------------------
#define AS_STRIDE 36
#define WS_STRIDE 132
#define OFF_ASHI 0
#define OFF_ASLO (128 * AS_STRIDE)
#define OFF_WSHI (2 * 128 * AS_STRIDE)
#define OFF_WSLO (2 * 128 * AS_STRIDE + 32 * WS_STRIDE)
#define DENSE_SMEM_FLOATS (2 * 128 * AS_STRIDE + 2 * 32 * WS_STRIDE)

__global__ __launch_bounds__(256, 1)
void dense_tc_kernel(const float* __restrict__ h,
                     const float* __restrict__ prev,
                     const float* __restrict__ time_diff,
                     float* __restrict__ out, int N, int layer)
{
    extern __shared__ float sm[];
    float* AsHi = sm + OFF_ASHI;
    float* AsLo = sm + OFF_ASLO;
    float* WsHi = sm + OFF_WSHI;
    float* WsLo = sm + OFF_WSLO;

    const float* whi = g_Whi + layer * 32768;
    const float* wlo = g_Wlo + layer * 32768;

    const int tid  = threadIdx.x;
    const int wid  = tid >> 5;
    const int lane = tid & 31;
    const int g = lane >> 2;
    const int t = lane & 3;
    const int mbase = (wid & 3) * 32;
    const int nbase = (wid >> 2) * 64;
    const int tileBase = blockIdx.x * 128;

    const int sr  = tid >> 1;
    const int sc0 = (tid & 1) * 16;
    const int snode = tileBase + sr;
    const bool sok = (snode < N);
    const float dec = sok ? __expf(-__ldg(time_diff + snode) * 0.1f) : 0.f;

    const int skk  = tid >> 3;
    const int swc0 = (tid & 7) * 16;

    // cp.async destinations for this thread's W slice (fixed across kc)
    const unsigned wsHiDst =
        (unsigned)__cvta_generic_to_shared(WsHi + skk * WS_STRIDE + swc0);
    const unsigned wsLoDst =
        (unsigned)__cvta_generic_to_shared(WsLo + skk * WS_STRIDE + swc0);

    float acc[2][8][4];
#pragma unroll
    for (int mi = 0; mi < 2; mi++)
#pragma unroll
        for (int nt = 0; nt < 8; nt++)
#pragma unroll
            for (int c = 0; c < 4; c++) acc[mi][nt][c] = 0.f;

#pragma unroll 1
    for (int kc = 0; kc < 8; kc++) {
        __syncthreads();
        // ---- kick off W staging via cp.async (no registers consumed) ----
        {
            const float* shi = whi + (kc * 32 + skk) * 128 + swc0;
            const float* slo = wlo + (kc * 32 + skk) * 128 + swc0;
#pragma unroll
            for (int j = 0; j < 4; j++) {
                CP_ASYNC16(wsHiDst + j * 16, shi + j * 4);
                CP_ASYNC16(wsLoDst + j * 16, slo + j * 4);
            }
            asm volatile("cp.async.commit_group;" ::: "memory");
        }
        // ---- stage A (fp32 -> tf32 hi/lo) while W copies in flight ----
        {
            float vals[16];
            if (sok) {
                const float* src = (kc < 4)
                    ? (h    + (size_t)snode * DD + kc * 32 + sc0)
                    : (prev + (size_t)snode * DD + (kc - 4) * 32 + sc0);
#pragma unroll
                for (int j = 0; j < 4; j++) {
                    float4 v = __ldg((const float4*)src + j);
                    vals[j * 4 + 0] = v.x; vals[j * 4 + 1] = v.y;
                    vals[j * 4 + 2] = v.z; vals[j * 4 + 3] = v.w;
                }
                if (kc >= 4) {
#pragma unroll
                    for (int j = 0; j < 16; j++) vals[j] *= dec;
                }
            } else {
#pragma unroll
                for (int j = 0; j < 16; j++) vals[j] = 0.f;
            }
            float his[16], los[16];
#pragma unroll
            for (int j = 0; j < 16; j++) {
                unsigned hb = f2tf32(vals[j]);
                his[j] = __uint_as_float(hb);
                los[j] = __uint_as_float(f2tf32(vals[j] - his[j]));
            }
            float* dhi = AsHi + sr * AS_STRIDE + sc0;
            float* dlo = AsLo + sr * AS_STRIDE + sc0;
#pragma unroll
            for (int j = 0; j < 4; j++) {
                ((float4*)dhi)[j] = make_float4(his[j*4], his[j*4+1], his[j*4+2], his[j*4+3]);
                ((float4*)dlo)[j] = make_float4(los[j*4], los[j*4+1], los[j*4+2], los[j*4+3]);
            }
        }
        asm volatile("cp.async.wait_group 0;" ::: "memory");
        __syncthreads();

#pragma unroll
        for (int ks = 0; ks < 4; ks++) {
            const int k0 = ks * 8;
            unsigned ahi[2][4], alo[2][4];
#pragma unroll
            for (int mi = 0; mi < 2; mi++) {
                int r0 = (mbase + mi * 16 + g) * AS_STRIDE + k0 + t;
                int r1 = r0 + 8 * AS_STRIDE;
                ahi[mi][0] = __float_as_uint(AsHi[r0]);
                ahi[mi][1] = __float_as_uint(AsHi[r1]);
                ahi[mi][2] = __float_as_uint(AsHi[r0 + 4]);
                ahi[mi][3] = __float_as_uint(AsHi[r1 + 4]);
                alo[mi][0] = __float_as_uint(AsLo[r0]);
                alo[mi][1] = __float_as_uint(AsLo[r1]);
                alo[mi][2] = __float_as_uint(AsLo[r0 + 4]);
                alo[mi][3] = __float_as_uint(AsLo[r1 + 4]);
            }
            unsigned bhi[8][2], blo[8][2];
#pragma unroll
            for (int nt = 0; nt < 8; nt++) {
                int col = nbase + nt * 8 + g;
                int i0 = (k0 + t) * WS_STRIDE + col;
                int i1 = i0 + 4 * WS_STRIDE;
                bhi[nt][0] = __float_as_uint(WsHi[i0]);
                bhi[nt][1] = __float_as_uint(WsHi[i1]);
                blo[nt][0] = __float_as_uint(WsLo[i0]);
                blo[nt][1] = __float_as_uint(WsLo[i1]);
            }
#pragma unroll
            for (int mi = 0; mi < 2; mi++)
#pragma unroll
                for (int nt = 0; nt < 8; nt++) {
                    MMA_TF32(acc[mi][nt], ahi[mi], bhi[nt]);
                    MMA_TF32(acc[mi][nt], ahi[mi], blo[nt]);
                    MMA_TF32(acc[mi][nt], alo[mi], bhi[nt]);
                }
        }
    }

#pragma unroll
    for (int mi = 0; mi < 2; mi++) {
        int row0 = tileBase + mbase + mi * 16 + g;
        int row1 = row0 + 8;
#pragma unroll
        for (int nt = 0; nt < 8; nt++) {
            int col = nbase + nt * 8 + 2 * t;
            if (row0 < N)
                *(float2*)(out + (size_t)row0 * DD + col) =
                    make_float2(acc[mi][nt][0], acc[mi][nt][1]);
            if (row1 < N)
                *(float2*)(out + (size_t)row1 * DD + col) =
                    make_float2(acc[mi][nt][2], acc[mi][nt][3]);
        }
    }
}

// ---------------------------------------------------------------------------
// Sort pipeline: counting sort of edges by relation type (R12 exact).
// ---------------------------------------------------------------------------
__global__ void zero_kernel(int R)
{
    int i = blockIdx.x * blockDim.x + threadIdx.x;
    if (i <= R) g_off[i] = 0;
    if (i < R)  g_cursor[i] = 0;
}

__global__ __launch_bounds__(256)
void hist_kernel(const int* __restrict__ etyp, int E, int R)
{
    __shared__ int lh[R_MAX];
    for (int i = threadIdx.x; i < R; i += blockDim.x) lh[i] = 0;
    __syncthreads();

    const int E4 = E >> 2;
    for (int q = blockIdx.x * blockDim.x + threadIdx.x; q < E4;
         q += gridDim.x * blockDim.x) {
        int4 tv = __ldg((const int4*)etyp + q);
        atomicAdd(&lh[tv.x], 1);
        atomicAdd(&lh[tv.y], 1);
        atomicAdd(&lh[tv.z], 1);
        atomicAdd(&lh[tv.w], 1);
    }
    int rem0 = E4 << 2;
    for (int e = rem0 + blockIdx.x * blockDim.x + threadIdx.x; e < E;
         e += gridDim.x * blockDim.x)
        atomicAdd(&lh[__ldg(etyp + e)], 1);
    __syncthreads();

    for (int i = threadIdx.x; i < R; i += blockDim.x) {
        int v = lh[i];
        if (v) atomicAdd(&g_off[i + 1], v);
    }
}

__global__ __launch_bounds__(512)
void scan_kernel(int R)
{
    __shared__ int buf[512];
    const int tid = threadIdx.x;
    buf[tid] = (tid <= R) ? g_off[tid] : 0;
    __syncthreads();
#pragma unroll
    for (int d = 1; d < 512; d <<= 1) {
        int v = (tid >= d) ? buf[tid - d] : 0;
        __syncthreads();
        buf[tid] += v;
        __syncthreads();
    }
    if (tid <= R) g_off[tid] = buf[tid];
}

__global__ __launch_bounds__(256)
void scatter_kernel(const int* __restrict__ esrc,
                    const int* __restrict__ edst,
                    const int* __restrict__ etyp,
                    const float* __restrict__ enorm,
                    const float* __restrict__ nnorm,
                    int E, int R)
{
    __shared__ int lbase[R_MAX];
    __shared__ int lcur[R_MAX];

    const int e0 = blockIdx.x * SCHUNK;
    const int e1 = min(e0 + SCHUNK, E);

    for (int i = threadIdx.x; i < R; i += blockDim.x) {
        lbase[i] = 0;
        lcur[i]  = 0;
    }
    __syncthreads();

    for (int e = e0 + threadIdx.x; e < e1; e += blockDim.x)
        atomicAdd(&lbase[__ldg(etyp + e)], 1);
    __syncthreads();

    for (int i = threadIdx.x; i < R; i += blockDim.x) {
        int cnt = lbase[i];
        lbase[i] = cnt ? (g_off[i] + atomicAdd(&g_cursor[i], cnt)) : 0;
    }
    __syncthreads();

    for (int e = e0 + threadIdx.x; e < e1; e += blockDim.x) {
        int t = __ldg(etyp + e);
        int d = __ldg(edst + e);
        int pos = lbase[t] + atomicAdd(&lcur[t], 1);
        float sc = __ldg(enorm + e) * __ldg(nnorm + d);
        g_edges[pos] = make_int4(__ldg(esrc + e), d, __float_as_int(sc), 0);
    }
}

// ---------------------------------------------------------------------------
// Sorted edge kernel, 2-wide (R12 exact).
// ---------------------------------------------------------------------------
__global__ __launch_bounds__(256)
void edge_sorted_kernel(const float* __restrict__ h,
                        const float* __restrict__ W,
                        float* __restrict__ out)
{
    const int t    = blockIdx.x;
    const int lane = threadIdx.x & 31;
    const int warp = threadIdx.x >> 5;

    const int start = g_off[t];
    const int end   = g_off[t + 1];
    if (start >= end) return;

    const float4* wp = (const float4*)(W + (size_t)t * 512) + lane * 4;
    const float4 w0 = __ldg(wp + 0);
    const float4 w1 = __ldg(wp + 1);
    const float4 w2 = __ldg(wp + 2);
    const float4 w3 = __ldg(wp + 3);

    const int stride = 8 * SPLIT;
    int e = start + blockIdx.y * 8 + warp;

    for (; e + stride < end; e += 2 * stride) {
        const int4 mdA = __ldg(g_edges + e);
        const int4 mdB = __ldg(g_edges + e + stride);

        float4 hA = __ldg((const float4*)(h + (size_t)mdA.x * DD) + lane);
        float4 hB = __ldg((const float4*)(h + (size_t)mdB.x * DD) + lane);

        const float scA = __int_as_float(mdA.z);
        const float scB = __int_as_float(mdB.z);

        float4 mA, mB;
        mA.x = hA.x * w0.x + hA.y * w1.x + hA.z * w2.x + hA.w * w3.x;
        mA.y = hA.x * w0.y + hA.y * w1.y + hA.z * w2.y + hA.w * w3.y;
        mA.z = hA.x * w0.z + hA.y * w1.z + hA.z * w2.z + hA.w * w3.z;
        mA.w = hA.x * w0.w + hA.y * w1.w + hA.z * w2.w + hA.w * w3.w;
        mB.x = hB.x * w0.x + hB.y * w1.x + hB.z * w2.x + hB.w * w3.x;
        mB.y = hB.x * w0.y + hB.y * w1.y + hB.z * w2.y + hB.w * w3.y;
        mB.z = hB.x * w0.z + hB.y * w1.z + hB.z * w2.z + hB.w * w3.z;
        mB.w = hB.x * w0.w + hB.y * w1.w + hB.z * w2.w + hB.w * w3.w;
        mA.x *= scA; mA.y *= scA; mA.z *= scA; mA.w *= scA;
        mB.x *= scB; mB.y *= scB; mB.z *= scB; mB.w *= scB;

        REDV4(out + (size_t)mdA.y * DD + lane * 4, mA);
        REDV4(out + (size_t)mdB.y * DD + lane * 4, mB);
    }

    if (e < end) {
        const int4 md = __ldg(g_edges + e);
        float4 hv = __ldg((const float4*)(h + (size_t)md.x * DD) + lane);
        const float sc = __int_as_float(md.z);

        float4 m;
        m.x = hv.x * w0.x + hv.y * w1.x + hv.z * w2.x + hv.w * w3.x;
        m.y = hv.x * w0.y + hv.y * w1.y + hv.z * w2.y + hv.w * w3.y;
        m.z = hv.x * w0.z + hv.y * w1.z + hv.z * w2.z + hv.w * w3.z;
        m.w = hv.x * w0.w + hv.y * w1.w + hv.z * w2.w + hv.w * w3.w;
        m.x *= sc; m.y *= sc; m.z *= sc; m.w *= sc;

        REDV4(out + (size_t)md.y * DD + lane * 4, m);
    }
}

__global__ void relu_kernel(float4* __restrict__ x, int n4)
{
    int i = blockIdx.x * blockDim.x + threadIdx.x;
    if (i < n4) {
        float4 v = x[i];
        v.x = fmaxf(v.x, 0.f);
        v.y = fmaxf(v.y, 0.f);
        v.z = fmaxf(v.z, 0.f);
        v.w = fmaxf(v.w, 0.f);
        x[i] = v;
    }
}

extern "C" void kernel_launch(void* const* d_in, const int* in_sizes, int n_in,
                              void* d_out, int out_size)
{
    const float* h   = (const float*)d_in[0];
    const float* fp  = (const float*)d_in[1];
    const float* sp  = (const float*)d_in[2];
    const float* td  = (const float*)d_in[3];
    const int*   es  = (const int*)  d_in[4];
    const int*   ed  = (const int*)  d_in[5];
    const int*   et  = (const int*)  d_in[6];
    const float* en  = (const float*)d_in[7];
    const float* nn  = (const float*)d_in[8];
    const float* W1  = (const float*)d_in[9];
    const float* W2  = (const float*)d_in[10];
    const float* lw1 = (const float*)d_in[11];
    const float* lw2 = (const float*)d_in[12];
    const float* tw1 = (const float*)d_in[13];
    const float* tw2 = (const float*)d_in[14];

    const int N = in_sizes[3];            // time_diff is (N,1)
    const int E = in_sizes[4];            // edge_src is (E,)
    const int R = in_sizes[9] / 512;      // W1 is (R, 512)

    float* h1 = (float*)d_out;
    float* h2 = h1 + (size_t)N * DD;

    const int denseBlocks   = (N + 127) / 128;
    const int scatterBlocks = (E + SCHUNK - 1) / SCHUNK;
    const int denseSmem     = DENSE_SMEM_FLOATS * sizeof(float);
    const int n4 = N * DD / 4;
    dim3 edgeGrid(R, SPLIT);

    cudaFuncSetAttribute(dense_tc_kernel,
                         cudaFuncAttributeMaxDynamicSharedMemorySize,
                         denseSmem);

    static cudaStream_t s2 = nullptr;
    static cudaEvent_t evFork = nullptr, evJoin = nullptr;
    if (s2 == nullptr) {
        cudaStreamCreateWithFlags(&s2, cudaStreamNonBlocking);
        cudaEventCreateWithFlags(&evFork, cudaEventDisableTiming);
        cudaEventCreateWithFlags(&evJoin, cudaEventDisableTiming);
    }

    // ---- fork: sort pipeline on s2, weight split + dense1 on main stream ----
    cudaEventRecord(evFork, 0);
    cudaStreamWaitEvent(s2, evFork, 0);

    zero_kernel   <<<(R + 256) / 256, 256, 0, s2>>>(R);
    hist_kernel   <<<256, 256, 0, s2>>>(et, E, R);
    scan_kernel   <<<1, 512, 0, s2>>>(R);
    scatter_kernel<<<scatterBlocks, 256, 0, s2>>>(es, ed, et, en, nn, E, R);
    cudaEventRecord(evJoin, s2);

    split_w_kernel<<<(2 * 256 * 128 + 255) / 256, 256>>>(lw1, tw1, lw2, tw2);
    dense_tc_kernel<<<denseBlocks, 256, denseSmem>>>(h, fp, td, h1, N, 0);

    // ---- join: edge1 needs both the sorted edges and the dense fill ----
    cudaStreamWaitEvent(0, evJoin, 0);
    edge_sorted_kernel<<<edgeGrid, 256>>>(h, W1, h1);

    // ---- layer 2 ----
    dense_tc_kernel<<<denseBlocks, 256, denseSmem>>>(h1, sp, td, h2, N, 1);
    edge_sorted_kernel<<<edgeGrid, 256>>>(h1, W2, h2);
    relu_kernel<<<(n4 + 255) / 256, 256>>>((float4*)h2, n4);
}

// round 16
// speedup vs baseline: 1.0724x; 1.0336x over previous
#include <cuda_runtime.h>

#define DD 128
#define E_MAX 800000
#define R_MAX 512
#define SPLIT 8
#define SCHUNK 4096

// ---- scratch (device globals; no allocation allowed) ----
__device__ int   g_off[R_MAX + 1];
__device__ int   g_cursor[R_MAX];
__device__ int4  g_edges[E_MAX];           // sorted {src, dst, scale_bits, pad}
__device__ float g_Whi[2 * 256 * 128];     // stacked [loop_w; time_w], tf32 hi
__device__ float g_Wlo[2 * 256 * 128];     // tf32 lo

#define REDV4(ptr, v)                                                   \
    asm volatile("red.global.add.v4.f32 [%0], {%1,%2,%3,%4};"           \
                 :: "l"(ptr), "f"((v).x), "f"((v).y), "f"((v).z), "f"((v).w) \
                 : "memory")

#define MMA_TF32(c, a, b)                                               \
    asm volatile("mma.sync.aligned.m16n8k8.row.col.f32.tf32.tf32.f32 "  \
                 "{%0,%1,%2,%3}, {%4,%5,%6,%7}, {%8,%9}, {%0,%1,%2,%3};" \
                 : "+f"((c)[0]), "+f"((c)[1]), "+f"((c)[2]), "+f"((c)[3]) \
                 : "r"((a)[0]), "r"((a)[1]), "r"((a)[2]), "r"((a)[3]),  \
                   "r"((b)[0]), "r"((b)[1]))

__device__ __forceinline__ unsigned f2tf32(float v)
{
    unsigned r;
    asm("cvt.rna.tf32.f32 %0, %1;" : "=r"(r) : "f"(v));
    return r;
}

// ---------------------------------------------------------------------------
// Weight split: W' = [loop_w; time_w] (256x128) -> tf32 hi/lo, both layers.
// ---------------------------------------------------------------------------
__global__ void split_w_kernel(const float* __restrict__ lw1,
                               const float* __restrict__ tw1,
                               const float* __restrict__ lw2,
                               const float* __restrict__ tw2)
{
    int idx = blockIdx.x * blockDim.x + threadIdx.x;
    if (idx >= 2 * 256 * 128) return;
    int layer = idx >> 15;
    int k = (idx >> 7) & 255;
    int n = idx & 127;
    const float* lw = layer ? lw2 : lw1;
    const float* tw = layer ? tw2 : tw1;
    float v = (k < 128) ? lw[k * 128 + n] : tw[(k - 128) * 128 + n];
    unsigned hb = f2tf32(v);
    float lo = v - __uint_as_float(hb);
    g_Whi[idx] = __uint_as_float(hb);
    g_Wlo[idx] = __uint_as_float(f2tf32(lo));
}

// ---------------------------------------------------------------------------
// Tensor-core dense kernel (3xTF32), R12 exact:
//   out[n,:] = [h[n,:], dec(n)*prev[n,:]] @ W'  (K=256)
// ---------------------------------------------------------------------------
#define AS_STRIDE 36
#define WS_STRIDE 132
#define OFF_ASHI 0
#define OFF_ASLO (128 * AS_STRIDE)
#define OFF_WSHI (2 * 128 * AS_STRIDE)
#define OFF_WSLO (2 * 128 * AS_STRIDE + 32 * WS_STRIDE)
#define DENSE_SMEM_FLOATS (2 * 128 * AS_STRIDE + 2 * 32 * WS_STRIDE)

__global__ __launch_bounds__(256, 1)
void dense_tc_kernel(const float* __restrict__ h,
                     const float* __restrict__ prev,
                     const float* __restrict__ time_diff,
                     float* __restrict__ out, int N, int layer)
{
    extern __shared__ float sm[];
    float* AsHi = sm + OFF_ASHI;
    float* AsLo = sm + OFF_ASLO;
    float* WsHi = sm + OFF_WSHI;
    float* WsLo = sm + OFF_WSLO;

    const float* whi = g_Whi + layer * 32768;
    const float* wlo = g_Wlo + layer * 32768;

    const int tid  = threadIdx.x;
    const int wid  = tid >> 5;
    const int lane = tid & 31;
    const int g = lane >> 2;
    const int t = lane & 3;
    const int mbase = (wid & 3) * 32;
    const int nbase = (wid >> 2) * 64;
    const int tileBase = blockIdx.x * 128;

    const int sr  = tid >> 1;
    const int sc0 = (tid & 1) * 16;
    const int snode = tileBase + sr;
    const bool sok = (snode < N);
    const float dec = sok ? __expf(-__ldg(time_diff + snode) * 0.1f) : 0.f;

    const int skk  = tid >> 3;
    const int swc0 = (tid & 7) * 16;

    float acc[2][8][4];
#pragma unroll
    for (int mi = 0; mi < 2; mi++)
#pragma unroll
        for (int nt = 0; nt < 8; nt++)
#pragma unroll
            for (int c = 0; c < 4; c++) acc[mi][nt][c] = 0.f;

#pragma unroll 1
    for (int kc = 0; kc < 8; kc++) {
        __syncthreads();
        {
            float vals[16];
            if (sok) {
                const float* src = (kc < 4)
                    ? (h    + (size_t)snode * DD + kc * 32 + sc0)
                    : (prev + (size_t)snode * DD + (kc - 4) * 32 + sc0);
#pragma unroll
                for (int j = 0; j < 4; j++) {
                    float4 v = __ldg((const float4*)src + j);
                    vals[j * 4 + 0] = v.x; vals[j * 4 + 1] = v.y;
                    vals[j * 4 + 2] = v.z; vals[j * 4 + 3] = v.w;
                }
                if (kc >= 4) {
#pragma unroll
                    for (int j = 0; j < 16; j++) vals[j] *= dec;
                }
            } else {
#pragma unroll
                for (int j = 0; j < 16; j++) vals[j] = 0.f;
            }
            float his[16], los[16];
#pragma unroll
            for (int j = 0; j < 16; j++) {
                unsigned hb = f2tf32(vals[j]);
                his[j] = __uint_as_float(hb);
                los[j] = __uint_as_float(f2tf32(vals[j] - his[j]));
            }
            float* dhi = AsHi + sr * AS_STRIDE + sc0;
            float* dlo = AsLo + sr * AS_STRIDE + sc0;
#pragma unroll
            for (int j = 0; j < 4; j++) {
                ((float4*)dhi)[j] = make_float4(his[j*4], his[j*4+1], his[j*4+2], his[j*4+3]);
                ((float4*)dlo)[j] = make_float4(los[j*4], los[j*4+1], los[j*4+2], los[j*4+3]);
            }
        }
        {
            const float* shi = whi + (kc * 32 + skk) * 128 + swc0;
            const float* slo = wlo + (kc * 32 + skk) * 128 + swc0;
            float* dhi = WsHi + skk * WS_STRIDE + swc0;
            float* dlo = WsLo + skk * WS_STRIDE + swc0;
#pragma unroll
            for (int j = 0; j < 4; j++) {
                ((float4*)dhi)[j] = __ldg((const float4*)shi + j);
                ((float4*)dlo)[j] = __ldg((const float4*)slo + j);
            }
        }
        __syncthreads();

#pragma unroll
        for (int ks = 0; ks < 4; ks++) {
            const int k0 = ks * 8;
            unsigned ahi[2][4], alo[2][4];
#pragma unroll
            for (int mi = 0; mi < 2; mi++) {
                int r0 = (mbase + mi * 16 + g) * AS_STRIDE + k0 + t;
                int r1 = r0 + 8 * AS_STRIDE;
                ahi[mi][0] = __float_as_uint(AsHi[r0]);
                ahi[mi][1] = __float_as_uint(AsHi[r1]);
                ahi[mi][2] = __float_as_uint(AsHi[r0 + 4]);
                ahi[mi][3] = __float_as_uint(AsHi[r1 + 4]);
                alo[mi][0] = __float_as_uint(AsLo[r0]);
                alo[mi][1] = __float_as_uint(AsLo[r1]);
                alo[mi][2] = __float_as_uint(AsLo[r0 + 4]);
                alo[mi][3] = __float_as_uint(AsLo[r1 + 4]);
            }
            unsigned bhi[8][2], blo[8][2];
#pragma unroll
            for (int nt = 0; nt < 8; nt++) {
                int col = nbase + nt * 8 + g;
                int i0 = (k0 + t) * WS_STRIDE + col;
                int i1 = i0 + 4 * WS_STRIDE;
                bhi[nt][0] = __float_as_uint(WsHi[i0]);
                bhi[nt][1] = __float_as_uint(WsHi[i1]);
                blo[nt][0] = __float_as_uint(WsLo[i0]);
                blo[nt][1] = __float_as_uint(WsLo[i1]);
            }
#pragma unroll
            for (int mi = 0; mi < 2; mi++)
#pragma unroll
                for (int nt = 0; nt < 8; nt++) {
                    MMA_TF32(acc[mi][nt], ahi[mi], bhi[nt]);
                    MMA_TF32(acc[mi][nt], ahi[mi], blo[nt]);
                    MMA_TF32(acc[mi][nt], alo[mi], bhi[nt]);
                }
        }
    }

#pragma unroll
    for (int mi = 0; mi < 2; mi++) {
        int row0 = tileBase + mbase + mi * 16 + g;
        int row1 = row0 + 8;
#pragma unroll
        for (int nt = 0; nt < 8; nt++) {
            int col = nbase + nt * 8 + 2 * t;
            if (row0 < N)
                *(float2*)(out + (size_t)row0 * DD + col) =
                    make_float2(acc[mi][nt][0], acc[mi][nt][1]);
            if (row1 < N)
                *(float2*)(out + (size_t)row1 * DD + col) =
                    make_float2(acc[mi][nt][2], acc[mi][nt][3]);
        }
    }
}

// ---------------------------------------------------------------------------
// Sort pipeline: counting sort of edges by relation type (R12 exact).
// ---------------------------------------------------------------------------
__global__ void zero_kernel(int R)
{
    int i = blockIdx.x * blockDim.x + threadIdx.x;
    if (i <= R) g_off[i] = 0;
    if (i < R)  g_cursor[i] = 0;
}

__global__ __launch_bounds__(256)
void hist_kernel(const int* __restrict__ etyp, int E, int R)
{
    __shared__ int lh[R_MAX];
    for (int i = threadIdx.x; i < R; i += blockDim.x) lh[i] = 0;
    __syncthreads();

    const int E4 = E >> 2;
    for (int q = blockIdx.x * blockDim.x + threadIdx.x; q < E4;
         q += gridDim.x * blockDim.x) {
        int4 tv = __ldg((const int4*)etyp + q);
        atomicAdd(&lh[tv.x], 1);
        atomicAdd(&lh[tv.y], 1);
        atomicAdd(&lh[tv.z], 1);
        atomicAdd(&lh[tv.w], 1);
    }
    int rem0 = E4 << 2;
    for (int e = rem0 + blockIdx.x * blockDim.x + threadIdx.x; e < E;
         e += gridDim.x * blockDim.x)
        atomicAdd(&lh[__ldg(etyp + e)], 1);
    __syncthreads();

    for (int i = threadIdx.x; i < R; i += blockDim.x) {
        int v = lh[i];
        if (v) atomicAdd(&g_off[i + 1], v);
    }
}

__global__ __launch_bounds__(512)
void scan_kernel(int R)
{
    __shared__ int buf[512];
    const int tid = threadIdx.x;
    buf[tid] = (tid <= R) ? g_off[tid] : 0;
    __syncthreads();
#pragma unroll
    for (int d = 1; d < 512; d <<= 1) {
        int v = (tid >= d) ? buf[tid - d] : 0;
        __syncthreads();
        buf[tid] += v;
        __syncthreads();
    }
    if (tid <= R) g_off[tid] = buf[tid];
}

__global__ __launch_bounds__(256)
void scatter_kernel(const int* __restrict__ esrc,
                    const int* __restrict__ edst,
                    const int* __restrict__ etyp,
                    const float* __restrict__ enorm,
                    const float* __restrict__ nnorm,
                    int E, int R)
{
    __shared__ int lbase[R_MAX];
    __shared__ int lcur[R_MAX];

    const int e0 = blockIdx.x * SCHUNK;
    const int e1 = min(e0 + SCHUNK, E);

    for (int i = threadIdx.x; i < R; i += blockDim.x) {
        lbase[i] = 0;
        lcur[i]  = 0;
    }
    __syncthreads();

    for (int e = e0 + threadIdx.x; e < e1; e += blockDim.x)
        atomicAdd(&lbase[__ldg(etyp + e)], 1);
    __syncthreads();

    for (int i = threadIdx.x; i < R; i += blockDim.x) {
        int cnt = lbase[i];
        lbase[i] = cnt ? (g_off[i] + atomicAdd(&g_cursor[i], cnt)) : 0;
    }
    __syncthreads();

    for (int e = e0 + threadIdx.x; e < e1; e += blockDim.x) {
        int t = __ldg(etyp + e);
        int d = __ldg(edst + e);
        int pos = lbase[t] + atomicAdd(&lcur[t], 1);
        float sc = __ldg(enorm + e) * __ldg(nnorm + d);
        g_edges[pos] = make_int4(__ldg(esrc + e), d, __float_as_int(sc), 0);
    }
}

// ---------------------------------------------------------------------------
// Sorted edge kernel, 2-wide with METADATA PREFETCH: next iteration's md
// loads issue before this iteration's compute, breaking the md->gather
// serial chain (md latency hidden one iteration ahead).
// ---------------------------------------------------------------------------
__global__ __launch_bounds__(256)
void edge_sorted_kernel(const float* __restrict__ h,
                        const float* __restrict__ W,
                        float* __restrict__ out)
{
    const int t    = blockIdx.x;
    const int lane = threadIdx.x & 31;
    const int warp = threadIdx.x >> 5;

    const int start = g_off[t];
    const int end   = g_off[t + 1];
    if (start >= end) return;

    const float4* wp = (const float4*)(W + (size_t)t * 512) + lane * 4;
    const float4 w0 = __ldg(wp + 0);
    const float4 w1 = __ldg(wp + 1);
    const float4 w2 = __ldg(wp + 2);
    const float4 w3 = __ldg(wp + 3);

    const int stride = 8 * SPLIT;
    int e = start + blockIdx.y * 8 + warp;

    // prologue: load first pair's metadata
    int4 mdA, mdB;
    bool haveA = (e < end);
    bool haveB = (e + stride < end);
    if (haveA) mdA = __ldg(g_edges + e);
    if (haveB) mdB = __ldg(g_edges + e + stride);

    while (haveB) {
        // issue gathers for current pair (md already resident)
        float4 hA = __ldg((const float4*)(h + (size_t)mdA.x * DD) + lane);
        float4 hB = __ldg((const float4*)(h + (size_t)mdB.x * DD) + lane);

        // prefetch next pair's metadata (overlaps with gathers + compute)
        const int en = e + 2 * stride;
        const bool nHaveA = (en < end);
        const bool nHaveB = (en + stride < end);
        int4 nmdA, nmdB;
        if (nHaveA) nmdA = __ldg(g_edges + en);
        if (nHaveB) nmdB = __ldg(g_edges + en + stride);

        const float scA = __int_as_float(mdA.z);
        const float scB = __int_as_float(mdB.z);

        float4 mA, mB;
        mA.x = hA.x * w0.x + hA.y * w1.x + hA.z * w2.x + hA.w * w3.x;
        mA.y = hA.x * w0.y + hA.y * w1.y + hA.z * w2.y + hA.w * w3.y;
        mA.z = hA.x * w0.z + hA.y * w1.z + hA.z * w2.z + hA.w * w3.z;
        mA.w = hA.x * w0.w + hA.y * w1.w + hA.z * w2.w + hA.w * w3.w;
        mB.x = hB.x * w0.x + hB.y * w1.x + hB.z * w2.x + hB.w * w3.x;
        mB.y = hB.x * w0.y + hB.y * w1.y + hB.z * w2.y + hB.w * w3.y;
        mB.z = hB.x * w0.z + hB.y * w1.z + hB.z * w2.z + hB.w * w3.z;
        mB.w = hB.x * w0.w + hB.y * w1.w + hB.z * w2.w + hB.w * w3.w;
        mA.x *= scA; mA.y *= scA; mA.z *= scA; mA.w *= scA;
        mB.x *= scB; mB.y *= scB; mB.z *= scB; mB.w *= scB;

        REDV4(out + (size_t)mdA.y * DD + lane * 4, mA);
        REDV4(out + (size_t)mdB.y * DD + lane * 4, mB);

        e = en;
        mdA = nmdA; mdB = nmdB;
        haveA = nHaveA; haveB = nHaveB;
    }

    // tail: at most one edge left (mdA already loaded if haveA)
    if (haveA) {
        float4 hv = __ldg((const float4*)(h + (size_t)mdA.x * DD) + lane);
        const float sc = __int_as_float(mdA.z);

        float4 m;
        m.x = hv.x * w0.x + hv.y * w1.x + hv.z * w2.x + hv.w * w3.x;
        m.y = hv.x * w0.y + hv.y * w1.y + hv.z * w2.y + hv.w * w3.y;
        m.z = hv.x * w0.z + hv.y * w1.z + hv.z * w2.z + hv.w * w3.z;
        m.w = hv.x * w0.w + hv.y * w1.w + hv.z * w2.w + hv.w * w3.w;
        m.x *= sc; m.y *= sc; m.z *= sc; m.w *= sc;

        REDV4(out + (size_t)mdA.y * DD + lane * 4, m);
    }
}

__global__ void relu_kernel(float4* __restrict__ x, int n4)
{
    int i = blockIdx.x * blockDim.x + threadIdx.x;
    if (i < n4) {
        float4 v = x[i];
        v.x = fmaxf(v.x, 0.f);
        v.y = fmaxf(v.y, 0.f);
        v.z = fmaxf(v.z, 0.f);
        v.w = fmaxf(v.w, 0.f);
        x[i] = v;
    }
}

extern "C" void kernel_launch(void* const* d_in, const int* in_sizes, int n_in,
                              void* d_out, int out_size)
{
    const float* h   = (const float*)d_in[0];
    const float* fp  = (const float*)d_in[1];
    const float* sp  = (const float*)d_in[2];
    const float* td  = (const float*)d_in[3];
    const int*   es  = (const int*)  d_in[4];
    const int*   ed  = (const int*)  d_in[5];
    const int*   et  = (const int*)  d_in[6];
    const float* en  = (const float*)d_in[7];
    const float* nn  = (const float*)d_in[8];
    const float* W1  = (const float*)d_in[9];
    const float* W2  = (const float*)d_in[10];
    const float* lw1 = (const float*)d_in[11];
    const float* lw2 = (const float*)d_in[12];
    const float* tw1 = (const float*)d_in[13];
    const float* tw2 = (const float*)d_in[14];

    const int N = in_sizes[3];            // time_diff is (N,1)
    const int E = in_sizes[4];            // edge_src is (E,)
    const int R = in_sizes[9] / 512;      // W1 is (R, 512)

    float* h1 = (float*)d_out;
    float* h2 = h1 + (size_t)N * DD;

    const int denseBlocks   = (N + 127) / 128;
    const int scatterBlocks = (E + SCHUNK - 1) / SCHUNK;
    const int denseSmem     = DENSE_SMEM_FLOATS * sizeof(float);
    const int n4 = N * DD / 4;
    dim3 edgeGrid(R, SPLIT);

    cudaFuncSetAttribute(dense_tc_kernel,
                         cudaFuncAttributeMaxDynamicSharedMemorySize,
                         denseSmem);

    static cudaStream_t s2 = nullptr;
    static cudaEvent_t evFork = nullptr, evJoin = nullptr;
    if (s2 == nullptr) {
        cudaStreamCreateWithFlags(&s2, cudaStreamNonBlocking);
        cudaEventCreateWithFlags(&evFork, cudaEventDisableTiming);
        cudaEventCreateWithFlags(&evJoin, cudaEventDisableTiming);
    }

    // ---- fork: sort pipeline on s2, weight split + dense1 on main stream ----
    cudaEventRecord(evFork, 0);
    cudaStreamWaitEvent(s2, evFork, 0);

    zero_kernel   <<<(R + 256) / 256, 256, 0, s2>>>(R);
    hist_kernel   <<<256, 256, 0, s2>>>(et, E, R);
    scan_kernel   <<<1, 512, 0, s2>>>(R);
    scatter_kernel<<<scatterBlocks, 256, 0, s2>>>(es, ed, et, en, nn, E, R);
    cudaEventRecord(evJoin, s2);

    split_w_kernel<<<(2 * 256 * 128 + 255) / 256, 256>>>(lw1, tw1, lw2, tw2);
    dense_tc_kernel<<<denseBlocks, 256, denseSmem>>>(h, fp, td, h1, N, 0);

    // ---- join: edge1 needs both the sorted edges and the dense fill ----
    cudaStreamWaitEvent(0, evJoin, 0);
    edge_sorted_kernel<<<edgeGrid, 256>>>(h, W1, h1);

    // ---- layer 2 ----
    dense_tc_kernel<<<denseBlocks, 256, denseSmem>>>(h1, sp, td, h2, N, 1);
    edge_sorted_kernel<<<edgeGrid, 256>>>(h1, W2, h2);
    relu_kernel<<<(n4 + 255) / 256, 256>>>((float4*)h2, n4);
}